// round 16
// baseline (speedup 1.0000x reference)
#include <cuda_runtime.h>
#include <cuda.h>
#include <cuda_fp16.h>
#include <cstdint>
#include <math.h>

constexpr int HDIM = 768;
constexpr int SEQ  = 256;
constexpr int NB   = 16;
constexpr int NK   = 32;
constexpr int KC   = 64;           // K elems per chunk (full 128B row)
constexpr int NCHUNK = HDIM / KC;  // 12
constexpr int BM   = 128;
constexpr int THREADS = 512;

__device__ __half g_qh[NB * SEQ * HDIM];
__device__ __half g_kh[NK * SEQ * HDIM];

// smem: two buffers of 384 rows x 128B (A rows 0-127, B rows 128-383), then aux
constexpr int BUFSZ    = 384 * 128;           // 49152
constexpr int OFF_AUX  = 2 * BUFSZ;           // 98304
constexpr int OFF_WTAB = OFF_AUX;             // 256 f32 (scale folded in)
constexpr int OFF_KMF  = OFF_AUX + 1024;      // 256 f32
constexpr int OFF_NUM  = OFF_AUX + 2048;      // 128*4 f32
constexpr int OFF_DEN  = OFF_AUX + 4096;      // 128*4 f32
constexpr int OFF_WSUM = OFF_AUX + 6144;      // 4 f32
constexpr int OFF_MBAR = OFF_AUX + 6208;      // full0, full1, drain0, drain1
constexpr int SMEM_TOTAL = OFF_AUX + 6272;    // 104576

__device__ __forceinline__ uint32_t smem_u32(const void* p) {
    uint32_t a;
    asm("{ .reg .u64 t; cvta.to.shared.u64 t, %1; cvt.u32.u64 %0, t; }" : "=r"(a) : "l"(p));
    return a;
}
#define MBAR_INIT(a, c) \
    asm volatile("mbarrier.init.shared.b64 [%0], %1;" :: "r"(a), "r"(c) : "memory")
#define MBAR_ARRIVE(a) \
    asm volatile("mbarrier.arrive.shared.b64 _, [%0];" :: "r"(a) : "memory")
#define MBAR_EXPECT_TX(a, bytes) \
    asm volatile("mbarrier.arrive.expect_tx.shared.b64 _, [%0], %1;" :: "r"(a), "r"(bytes) : "memory")
#define MBAR_WAIT(mbar_addr, phase) do {                                                      \
    uint32_t _m = (uint32_t)(mbar_addr), _p = (uint32_t)(phase), _d;                          \
    asm volatile("{\n\t.reg .pred p;\n\t"                                                     \
        "mbarrier.try_wait.parity.acquire.cta.shared::cta.b64 p, [%1], %2;\n\t"               \
        "selp.b32 %0, 1, 0, p;\n\t}" : "=r"(_d) : "r"(_m), "r"(_p) : "memory");               \
    if (!_d) {                                                                                \
        asm volatile("{\n\t.reg .pred P1;\n\tWL_%=:\n\t"                                      \
            "mbarrier.try_wait.parity.acquire.cta.shared::cta.b64 P1, [%0], %1, 0x989680;\n\t"\
            "@P1 bra.uni WD_%=;\n\tbra.uni WL_%=;\n\tWD_%=:\n\t}"                             \
            :: "r"(_m), "r"(_p) : "memory");                                                  \
    }                                                                                         \
} while (0)
#define TMA_LOAD_2D(smem_addr, tmap, cx, cy, mbar) \
    asm volatile("cp.async.bulk.tensor.2d.shared::cta.global.tile.mbarrier::complete_tx::bytes " \
                 "[%0], [%1, {%2, %3}], [%4];" \
                 :: "r"((uint32_t)(smem_addr)), "l"(tmap), "r"((int32_t)(cx)), "r"((int32_t)(cy)), \
                    "r"((uint32_t)(mbar)) : "memory")

__device__ __forceinline__ void ldsm4(uint32_t* r, uint32_t addr) {
    asm volatile("ldmatrix.sync.aligned.m8n8.x4.shared.b16 {%0,%1,%2,%3}, [%4];"
                 : "=r"(r[0]), "=r"(r[1]), "=r"(r[2]), "=r"(r[3]) : "r"(addr));
}
__device__ __forceinline__ void mma16816(float* d, const uint32_t* a, uint32_t b0, uint32_t b1) {
    asm volatile("mma.sync.aligned.m16n8k16.row.col.f32.f16.f16.f32 "
                 "{%0,%1,%2,%3}, {%4,%5,%6,%7}, {%8,%9}, {%0,%1,%2,%3};"
                 : "+f"(d[0]), "+f"(d[1]), "+f"(d[2]), "+f"(d[3])
                 : "r"(a[0]), "r"(a[1]), "r"(a[2]), "r"(a[3]), "r"(b0), "r"(b1));
}

// float4 loads, paired half2 stores; 192 threads per token
__global__ void normalize_kernel(const float* __restrict__ q, const float* __restrict__ k,
                                 float* __restrict__ out) {
    int tok = blockIdx.x;
    int tid = threadIdx.x;   // 0..191
    if (tok == 0) {
        for (int i = tid; i < NB * NK; i += 192) out[i] = 0.0f;
    }
    bool isq = tok < NB * SEQ;
    int t2 = isq ? tok : tok - NB * SEQ;
    const float4* src = (const float4*)((isq ? q : k) + (size_t)t2 * HDIM);
    float4 v = src[tid];
    float ss = v.x * v.x + v.y * v.y + v.z * v.z + v.w * v.w;
#pragma unroll
    for (int o = 16; o; o >>= 1) ss += __shfl_xor_sync(0xffffffffu, ss, o);
    __shared__ float red[6];
    __shared__ float total;
    if ((tid & 31) == 0) red[tid >> 5] = ss;
    __syncthreads();
    if (tid == 0) {
        float s = 0.0f;
#pragma unroll
        for (int w = 0; w < 6; w++) s += red[w];
        total = s;
    }
    __syncthreads();
    float inv = 1.0f / fmaxf(sqrtf(total), 1e-12f);
    __half2 h0, h1;
    h0.x = __float2half(v.x * inv); h0.y = __float2half(v.y * inv);
    h1.x = __float2half(v.z * inv); h1.y = __float2half(v.w * inv);
    __half2* dst = (__half2*)((isq ? g_qh : g_kh) + (size_t)t2 * HDIM) + 2 * tid;
    dst[0] = h0;
    dst[1] = h1;
}

__global__ __launch_bounds__(THREADS, 1)
void li_hmma(const __grid_constant__ CUtensorMap tmA,
             const __grid_constant__ CUtensorMap tmB,
             const float* __restrict__ plsc, const float* __restrict__ paraw,
             const int* __restrict__ qmask, const int* __restrict__ kmask,
             float* __restrict__ out) {
    extern __shared__ __align__(1024) char smem[];
    const uint32_t sb = smem_u32(smem);
    const int tid = threadIdx.x, lane = tid & 31, wid = tid >> 5;
    const int mb = blockIdx.x, jb = blockIdx.y, ib = blockIdx.z;

    float* wt   = (float*)(smem + OFF_WTAB);
    float* kf   = (float*)(smem + OFF_KMF);
    float* nums = (float*)(smem + OFF_NUM);
    float* dens = (float*)(smem + OFF_DEN);
    float* wsum = (float*)(smem + OFF_WSUM);
    const uint32_t mfull0 = sb + OFF_MBAR,      mfull1 = sb + OFF_MBAR + 8;
    const uint32_t mdr0   = sb + OFF_MBAR + 16, mdr1   = sb + OFF_MBAR + 24;

    const int aq = ib * SEQ + mb * BM;
    const int bk = jb * SEQ;

    const float scale = __expf(plsc[0]);
    const float ar = paraw[0];
    const float alpha = ar >= 0.0f ? ar : 0.01f * ar;
    if (tid < SEQ) {
        wt[tid] = scale * __expf(-alpha * (float)tid);   // scale folded in
        kf[tid] = (float)kmask[jb * SEQ + tid];
    }
    if (tid == 0) {
        MBAR_INIT(mfull0, 1); MBAR_INIT(mfull1, 1);
        MBAR_INIT(mdr0, 16);  MBAR_INIT(mdr1, 16);
    }
    __syncthreads();
    if (tid == 0) {
        MBAR_EXPECT_TX(mfull0, (uint32_t)BUFSZ);
        TMA_LOAD_2D(sb,                 &tmA, 0,  aq, mfull0);
        TMA_LOAD_2D(sb + 16384,         &tmB, 0,  bk, mfull0);
        MBAR_EXPECT_TX(mfull1, (uint32_t)BUFSZ);
        TMA_LOAD_2D(sb + BUFSZ,         &tmA, KC, aq, mfull1);
        TMA_LOAD_2D(sb + BUFSZ + 16384, &tmB, KC, bk, mfull1);
    }

    // ---- MMA: 4(m) x 4(n) warps; warp tile 32 x 64; single fp16 pass ----
    const int mw = wid >> 2, nw = wid & 3;
    const int l15 = lane & 15, lhi = lane >> 4;
    const uint32_t roA = (uint32_t)(mw * 32 + l15);
    const uint32_t roB = (uint32_t)(128 + nw * 64 + l15);
    const uint32_t baseA = sb + roA * 128u + ((((uint32_t)lhi ^ (roA & 7u)) & 7u) << 4);
    const uint32_t baseB = sb + roB * 128u + ((((uint32_t)lhi ^ (roB & 7u)) & 7u) << 4);

    float acc[2][8][4];
#pragma unroll
    for (int im = 0; im < 2; im++)
#pragma unroll
        for (int tl = 0; tl < 8; tl++)
#pragma unroll
            for (int cc = 0; cc < 4; cc++) acc[im][tl][cc] = 0.0f;

    auto compute = [&](uint32_t bo) {
        const uint32_t bA = baseA + bo, bB = baseB + bo;
#pragma unroll
        for (uint32_t ks = 0; ks < 4; ks++) {
            const uint32_t xa = bA ^ (ks << 5);
            const uint32_t xb = bB ^ (ks << 5);
            uint32_t a[2][4], b[4][4];
#pragma unroll
            for (int im = 0; im < 2; im++)
                ldsm4(a[im], xa + im * 2048u);
#pragma unroll
            for (int ng = 0; ng < 4; ng++)
                ldsm4(b[ng], xb + ng * 2048u);
#pragma unroll
            for (int ng = 0; ng < 4; ng++)
#pragma unroll
                for (int im = 0; im < 2; im++)
#pragma unroll
                    for (int o = 0; o < 2; o++)
                        mma16816(acc[im][ng * 2 + o], a[im], b[ng][o], b[ng][o + 2]);
        }
    };

    // ---- pipeline: full/drain mbarriers, no full-CTA barrier in the loop ----
#pragma unroll 1
    for (int it = 0; it < NCHUNK; ++it) {
        const uint32_t mf = (it & 1) ? mfull1 : mfull0;
        const uint32_t md = (it & 1) ? mdr1 : mdr0;
        const uint32_t p  = (uint32_t)((it >> 1) & 1);
        MBAR_WAIT(mf, p);
        compute((it & 1) ? (uint32_t)BUFSZ : 0u);
        if (lane == 0) MBAR_ARRIVE(md);
        if (it + 2 < NCHUNK && tid == 0) {
            MBAR_WAIT(md, p);   // all 16 warps drained this buffer for this phase
            const uint32_t dst = sb + ((it & 1) ? (uint32_t)BUFSZ : 0u);
            MBAR_EXPECT_TX(mf, (uint32_t)BUFSZ);
            TMA_LOAD_2D(dst,         &tmA, (it + 2) * KC, aq, mf);
            TMA_LOAD_2D(dst + 16384, &tmB, (it + 2) * KC, bk, mf);
        }
    }

    // ---- epilogue: softmax (no max-sub; |logit| <= scale) + sum p*C ----
    float pn[4] = {0, 0, 0, 0}, pd[4] = {0, 0, 0, 0};
    const int colq = 2 * (lane & 3);
    const int rowq = lane >> 2;
#pragma unroll
    for (int im = 0; im < 2; im++)
#pragma unroll
        for (int hh = 0; hh < 2; hh++) {
            const int r = mw * 32 + im * 16 + hh * 8 + rowq;
            const int s = mb * BM + r;
            const int slot = im * 2 + hh;
#pragma unroll
            for (int tl = 0; tl < 8; tl++)
#pragma unroll
                for (int e = 0; e < 2; e++) {
                    const float C = acc[im][tl][hh * 2 + e];
                    const int t = nw * 64 + tl * 8 + colq + e;
                    int d = s - t; d = d < 0 ? -d : d;
                    const float ex = kf[t] * __expf(wt[d] * C);
                    pd[slot] += ex;
                    pn[slot] += ex * C;
                }
        }
#pragma unroll
    for (int o = 1; o <= 2; o <<= 1)
#pragma unroll
        for (int k = 0; k < 4; k++) {
            pn[k] += __shfl_xor_sync(0xffffffffu, pn[k], o);
            pd[k] += __shfl_xor_sync(0xffffffffu, pd[k], o);
        }
    if ((lane & 3) == 0)
#pragma unroll
        for (int k = 0; k < 4; k++) {
            const int r = mw * 32 + (k >> 1) * 16 + (k & 1) * 8 + rowq;
            nums[r * 4 + nw] = pn[k];
            dens[r * 4 + nw] = pd[k];
        }
    __syncthreads();
    if (tid < BM) {
        float n = 0.0f, d = 0.0f;
#pragma unroll
        for (int w = 0; w < 4; w++) { n += nums[tid * 4 + w]; d += dens[tid * 4 + w]; }
        float pt = d > 0.0f ? n / d : 0.0f;
        pt *= (float)qmask[ib * SEQ + mb * BM + tid];
#pragma unroll
        for (int o = 16; o; o >>= 1) pt += __shfl_xor_sync(0xffffffffu, pt, o);
        if (lane == 0) wsum[tid >> 5] = pt;
    }
    __syncthreads();
    if (tid == 0)
        atomicAdd(&out[ib * NK + jb], wsum[0] + wsum[1] + wsum[2] + wsum[3]);
}

typedef CUresult (*EncodeFn)(CUtensorMap*, CUtensorMapDataType, cuuint32_t, void*,
                             const cuuint64_t*, const cuuint64_t*, const cuuint32_t*,
                             const cuuint32_t*, CUtensorMapInterleave, CUtensorMapSwizzle,
                             CUtensorMapL2promotion, CUtensorMapFloatOOBfill);

extern "C" void kernel_launch(void* const* d_in, const int* in_sizes, int n_in,
                              void* d_out, int out_size) {
    const float* q    = (const float*)d_in[0];
    const float* k    = (const float*)d_in[1];
    const float* lsc  = (const float*)d_in[2];
    const float* araw = (const float*)d_in[3];
    const int*   qm   = (const int*)d_in[4];
    const int*   km   = (const int*)d_in[5];
    float* out = (float*)d_out;

    void* qptr = nullptr; void* kptr = nullptr;
    cudaGetSymbolAddress(&qptr, g_qh);
    cudaGetSymbolAddress(&kptr, g_kh);
    EncodeFn enc = nullptr;
    cudaDriverEntryPointQueryResult qr;
#if CUDART_VERSION >= 12050
    cudaGetDriverEntryPointByVersion("cuTensorMapEncodeTiled", (void**)&enc, 12000,
                                     cudaEnableDefault, &qr);
#else
    cudaGetDriverEntryPoint("cuTensorMapEncodeTiled", (void**)&enc, cudaEnableDefault, &qr);
#endif
    CUtensorMap tmA, tmB;
    cuuint64_t gdA[2] = {(cuuint64_t)HDIM, (cuuint64_t)NB * SEQ};
    cuuint64_t gdB[2] = {(cuuint64_t)HDIM, (cuuint64_t)NK * SEQ};
    cuuint64_t gs[1]  = {(cuuint64_t)HDIM * 2};
    cuuint32_t boxA[2] = {64, 128}, boxB[2] = {64, 256}, es[2] = {1, 1};
    enc(&tmA, CU_TENSOR_MAP_DATA_TYPE_FLOAT16, 2, qptr, gdA, gs, boxA, es,
        CU_TENSOR_MAP_INTERLEAVE_NONE, CU_TENSOR_MAP_SWIZZLE_128B,
        CU_TENSOR_MAP_L2_PROMOTION_L2_128B, CU_TENSOR_MAP_FLOAT_OOB_FILL_NONE);
    enc(&tmB, CU_TENSOR_MAP_DATA_TYPE_FLOAT16, 2, kptr, gdB, gs, boxB, es,
        CU_TENSOR_MAP_INTERLEAVE_NONE, CU_TENSOR_MAP_SWIZZLE_128B,
        CU_TENSOR_MAP_L2_PROMOTION_L2_128B, CU_TENSOR_MAP_FLOAT_OOB_FILL_NONE);

    cudaFuncSetAttribute(li_hmma, cudaFuncAttributeMaxDynamicSharedMemorySize, SMEM_TOTAL);
    normalize_kernel<<<NB * SEQ + NK * SEQ, 192>>>(q, k, out);
    li_hmma<<<dim3(SEQ / BM, NK, NB), THREADS, SMEM_TOTAL>>>(tmA, tmB, lsc, araw, qm, km, out);
}

// round 17
// speedup vs baseline: 1.4723x; 1.4723x over previous
#include <cuda_runtime.h>
#include <cuda.h>
#include <cuda_fp16.h>
#include <cstdint>
#include <math.h>

constexpr int HDIM = 768;
constexpr int SEQ  = 256;
constexpr int NB   = 16;
constexpr int NK   = 32;
constexpr int KC   = 64;           // K elems per chunk (full 128B row)
constexpr int NCHUNK = HDIM / KC;  // 12
constexpr int BM   = 64;
constexpr int THREADS = 256;

// compacted fp16 normalized embeddings + compaction metadata
__device__ __half g_qc[NB * SEQ * HDIM];
__device__ __half g_kc[NK * SEQ * HDIM];
__device__ int    g_qslot[NB * SEQ];
__device__ int    g_kslot[NK * SEQ];
__device__ int    g_qidx[NB * SEQ];
__device__ int    g_kidx[NK * SEQ];
__device__ int    g_qn[NB];
__device__ int    g_kn[NK];

// smem: two buffers of 320 rows x 128B (A rows 0-63, B rows 64-319), then aux
constexpr int BUFSZ    = 320 * 128;           // 40960
constexpr int OFF_AUX  = 2 * BUFSZ;           // 81920
constexpr int OFF_WTAB = OFF_AUX;             // 256 f32 (scale folded in)
constexpr int OFF_KMF  = OFF_AUX + 1024;      // 256 f32 (t<nk validity)
constexpr int OFF_KID  = OFF_AUX + 2048;      // 256 i32 (orig k index)
constexpr int OFF_QID  = OFF_AUX + 3072;      // 64 i32 (orig q index)
constexpr int OFF_NUM  = OFF_AUX + 3328;      // 64*4 f32
constexpr int OFF_DEN  = OFF_AUX + 4352;      // 64*4 f32
constexpr int OFF_WSUM = OFF_AUX + 5376;      // 2 f32
constexpr int OFF_MBAR = OFF_AUX + 5440;      // full0, full1
constexpr int SMEM_TOTAL = OFF_AUX + 5456;

__device__ __forceinline__ uint32_t smem_u32(const void* p) {
    uint32_t a;
    asm("{ .reg .u64 t; cvta.to.shared.u64 t, %1; cvt.u32.u64 %0, t; }" : "=r"(a) : "l"(p));
    return a;
}
#define MBAR_INIT(a, c) \
    asm volatile("mbarrier.init.shared.b64 [%0], %1;" :: "r"(a), "r"(c) : "memory")
#define MBAR_EXPECT_TX(a, bytes) \
    asm volatile("mbarrier.arrive.expect_tx.shared.b64 _, [%0], %1;" :: "r"(a), "r"(bytes) : "memory")
#define MBAR_WAIT(mbar_addr, phase) do {                                                      \
    uint32_t _m = (uint32_t)(mbar_addr), _p = (uint32_t)(phase), _d;                          \
    asm volatile("{\n\t.reg .pred p;\n\t"                                                     \
        "mbarrier.try_wait.parity.acquire.cta.shared::cta.b64 p, [%1], %2;\n\t"               \
        "selp.b32 %0, 1, 0, p;\n\t}" : "=r"(_d) : "r"(_m), "r"(_p) : "memory");               \
    if (!_d) {                                                                                \
        asm volatile("{\n\t.reg .pred P1;\n\tWL_%=:\n\t"                                      \
            "mbarrier.try_wait.parity.acquire.cta.shared::cta.b64 P1, [%0], %1, 0x989680;\n\t"\
            "@P1 bra.uni WD_%=;\n\tbra.uni WL_%=;\n\tWD_%=:\n\t}"                             \
            :: "r"(_m), "r"(_p) : "memory");                                                  \
    }                                                                                         \
} while (0)
#define TMA_LOAD_2D(smem_addr, tmap, cx, cy, mbar) \
    asm volatile("cp.async.bulk.tensor.2d.shared::cta.global.tile.mbarrier::complete_tx::bytes " \
                 "[%0], [%1, {%2, %3}], [%4];" \
                 :: "r"((uint32_t)(smem_addr)), "l"(tmap), "r"((int32_t)(cx)), "r"((int32_t)(cy)), \
                    "r"((uint32_t)(mbar)) : "memory")

__device__ __forceinline__ void ldsm4(uint32_t* r, uint32_t addr) {
    asm volatile("ldmatrix.sync.aligned.m8n8.x4.shared.b16 {%0,%1,%2,%3}, [%4];"
                 : "=r"(r[0]), "=r"(r[1]), "=r"(r[2]), "=r"(r[3]) : "r"(addr));
}
__device__ __forceinline__ void mma16816(float* d, const uint32_t* a, uint32_t b0, uint32_t b1) {
    asm volatile("mma.sync.aligned.m16n8k16.row.col.f32.f16.f16.f32 "
                 "{%0,%1,%2,%3}, {%4,%5,%6,%7}, {%8,%9}, {%0,%1,%2,%3};"
                 : "+f"(d[0]), "+f"(d[1]), "+f"(d[2]), "+f"(d[3])
                 : "r"(a[0]), "r"(a[1]), "r"(a[2]), "r"(a[3]), "r"(b0), "r"(b1));
}

// ---------------------------------------------------------------------------
// prep: per-batch deterministic prefix-scan compaction metadata + zero pads
// grid = NB + NK blocks, 256 threads
// ---------------------------------------------------------------------------
__global__ void prep_kernel(const int* __restrict__ qm, const int* __restrict__ km,
                            float* __restrict__ out) {
    const int b = blockIdx.x, tid = threadIdx.x, lane = tid & 31, w = tid >> 5;
    if (b == 0) {
        out[tid] = 0.0f;
        out[tid + 256] = 0.0f;
    }
    const bool isq = b < NB;
    const int bb = isq ? b : b - NB;
    const int* m = (isq ? qm : km) + bb * SEQ;
    const int v = (m[tid] != 0) ? 1 : 0;
    const unsigned bal = __ballot_sync(0xffffffffu, v);
    const int wpre = __popc(bal & ((1u << lane) - 1u));
    __shared__ int wc[8], woff[9];
    if (lane == 31) wc[w] = wpre + v;
    __syncthreads();
    if (tid == 0) {
        int s = 0;
#pragma unroll
        for (int i = 0; i < 8; i++) { woff[i] = s; s += wc[i]; }
        woff[8] = s;
    }
    __syncthreads();
    const int slot = woff[w] + wpre;
    const int n = woff[8];
    int* slotA = (isq ? g_qslot : g_kslot) + bb * SEQ;
    int* idxA  = (isq ? g_qidx  : g_kidx)  + bb * SEQ;
    slotA[tid] = v ? slot : -1;
    if (v) idxA[slot] = tid;
    if (tid >= n) idxA[tid] = 0;
    if (tid == 0) { if (isq) g_qn[bb] = n; else g_kn[bb] = n; }
    const int pad = (n + 63) & ~63;
    if (tid >= n && tid < pad) {
        uint4* dst = (uint4*)((isq ? g_qc : g_kc) + (size_t)(bb * SEQ + tid) * HDIM);
        const uint4 z = {0, 0, 0, 0};
#pragma unroll
        for (int i = 0; i < 96; i++) dst[i] = z;
    }
}

// ---------------------------------------------------------------------------
// normalize: per-token block, writes directly to compacted slot (skip invalid)
// ---------------------------------------------------------------------------
__global__ void normalize_kernel(const float* __restrict__ q, const float* __restrict__ k) {
    const int tok = blockIdx.x;
    const int tid = threadIdx.x;   // 0..191
    const bool isq = tok < NB * SEQ;
    const int t2 = isq ? tok : tok - NB * SEQ;
    const int slot = (isq ? g_qslot : g_kslot)[t2];
    if (slot < 0) return;
    const float4* src = (const float4*)((isq ? q : k) + (size_t)t2 * HDIM);
    float4 v = src[tid];
    float ss = v.x * v.x + v.y * v.y + v.z * v.z + v.w * v.w;
#pragma unroll
    for (int o = 16; o; o >>= 1) ss += __shfl_xor_sync(0xffffffffu, ss, o);
    __shared__ float red[6];
    __shared__ float total;
    if ((tid & 31) == 0) red[tid >> 5] = ss;
    __syncthreads();
    if (tid == 0) {
        float s = 0.0f;
#pragma unroll
        for (int i = 0; i < 6; i++) s += red[i];
        total = s;
    }
    __syncthreads();
    const float inv = 1.0f / fmaxf(sqrtf(total), 1e-12f);
    __half2 h0, h1;
    h0.x = __float2half(v.x * inv); h0.y = __float2half(v.y * inv);
    h1.x = __float2half(v.z * inv); h1.y = __float2half(v.w * inv);
    const int batch = t2 >> 8;
    __half2* dst = (__half2*)((isq ? g_qc : g_kc) +
                              (size_t)(batch * SEQ + slot) * HDIM) + 2 * tid;
    dst[0] = h0;
    dst[1] = h1;
}

// ---------------------------------------------------------------------------
// main GEMM + fused softmax, on compacted tokens
// ---------------------------------------------------------------------------
__global__ __launch_bounds__(THREADS, 2)
void li_hmma(const __grid_constant__ CUtensorMap tmA,
             const __grid_constant__ CUtensorMap tmB,
             const float* __restrict__ plsc, const float* __restrict__ paraw,
             float* __restrict__ out) {
    const int mb = blockIdx.x, jb = blockIdx.y, ib = blockIdx.z;
    const int nq = g_qn[ib];
    if (mb * BM >= nq) return;            // tile fully masked -> contributes 0
    const int nk = g_kn[jb];
    const int ngB = (nk + 63) >> 6;       // active 64-col groups (0..4)
    const uint32_t txb = 8192u * (uint32_t)(1 + ngB);

    extern __shared__ __align__(1024) char smem[];
    const uint32_t sb = smem_u32(smem);
    const int tid = threadIdx.x, lane = tid & 31, wid = tid >> 5;

    float* wt   = (float*)(smem + OFF_WTAB);
    float* kf   = (float*)(smem + OFF_KMF);
    int*   kid  = (int*)(smem + OFF_KID);
    int*   qid  = (int*)(smem + OFF_QID);
    float* nums = (float*)(smem + OFF_NUM);
    float* dens = (float*)(smem + OFF_DEN);
    float* wsum = (float*)(smem + OFF_WSUM);
    const uint32_t mf0 = sb + OFF_MBAR, mf1 = sb + OFF_MBAR + 8;

    const int aq = ib * SEQ + mb * BM;    // compacted A row origin
    const int bk = jb * SEQ;              // compacted B row origin

    const float scale = __expf(plsc[0]);
    const float ar = paraw[0];
    const float alpha = ar >= 0.0f ? ar : 0.01f * ar;
    if (tid < SEQ) {
        wt[tid]  = scale * __expf(-alpha * (float)tid);
        kf[tid]  = (tid < nk) ? 1.0f : 0.0f;
        kid[tid] = g_kidx[jb * SEQ + tid];
    }
    if (tid < BM) qid[tid] = g_qidx[ib * SEQ + mb * BM + tid];
    if (tid == 0) { MBAR_INIT(mf0, 1); MBAR_INIT(mf1, 1); }
    __syncthreads();

    if (tid == 0) {
        MBAR_EXPECT_TX(mf0, txb);
        TMA_LOAD_2D(sb, &tmA, 0, aq, mf0);
        for (int g = 0; g < ngB; g++)
            TMA_LOAD_2D(sb + 8192 + g * 8192, &tmB, 0, bk + g * 64, mf0);
    }

    // ---- MMA: 2(m) x 4(n) warps; warp tile 32 x 64; single fp16 pass ----
    const int mw = wid >> 2, nw = wid & 3;
    const bool actB = (nw * 64) < nk;
    const int l15 = lane & 15, lhi = lane >> 4;
    const uint32_t roA = (uint32_t)(mw * 32 + l15);
    const uint32_t roB = (uint32_t)(64 + nw * 64 + l15);
    const uint32_t baseA = sb + roA * 128u + ((((uint32_t)lhi ^ (roA & 7u)) & 7u) << 4);
    const uint32_t baseB = sb + roB * 128u + ((((uint32_t)lhi ^ (roB & 7u)) & 7u) << 4);

    float acc[2][8][4];
#pragma unroll
    for (int im = 0; im < 2; im++)
#pragma unroll
        for (int tl = 0; tl < 8; tl++)
#pragma unroll
            for (int cc = 0; cc < 4; cc++) acc[im][tl][cc] = 0.0f;

    auto compute = [&](uint32_t bo) {
        const uint32_t bA = baseA + bo, bB = baseB + bo;
#pragma unroll
        for (uint32_t ks = 0; ks < 4; ks++) {
            const uint32_t xa = bA ^ (ks << 5);
            const uint32_t xb = bB ^ (ks << 5);
            uint32_t a[2][4], b[4][4];
#pragma unroll
            for (int im = 0; im < 2; im++)
                ldsm4(a[im], xa + im * 2048u);
#pragma unroll
            for (int ng = 0; ng < 4; ng++)
                ldsm4(b[ng], xb + ng * 2048u);
#pragma unroll
            for (int ng = 0; ng < 4; ng++)
#pragma unroll
                for (int im = 0; im < 2; im++)
#pragma unroll
                    for (int o = 0; o < 2; o++)
                        mma16816(acc[im][ng * 2 + o], a[im], b[ng][o], b[ng][o + 2]);
        }
    };

    // ---- pipeline: double buffer, one barrier per chunk (R13 scheme) ----
#pragma unroll 1
    for (int it = 0; it < NCHUNK; ++it) {
        MBAR_WAIT((it & 1) ? mf1 : mf0, (it >> 1) & 1);
        __syncthreads();   // chunk it visible; other buffer drained by compute(it-1)
        if (it + 1 < NCHUNK && tid == 0) {
            const uint32_t m = ((it + 1) & 1) ? mf1 : mf0;
            const uint32_t dst = sb + (((it + 1) & 1) ? (uint32_t)BUFSZ : 0u);
            MBAR_EXPECT_TX(m, txb);
            TMA_LOAD_2D(dst, &tmA, (it + 1) * KC, aq, m);
            for (int g = 0; g < ngB; g++)
                TMA_LOAD_2D(dst + 8192 + g * 8192, &tmB, (it + 1) * KC, bk + g * 64, m);
        }
        if (actB) compute((it & 1) ? (uint32_t)BUFSZ : 0u);
    }

    // ---- epilogue: softmax over valid k (orig-index distances) + sum p*C ----
    float pn[4] = {0, 0, 0, 0}, pd[4] = {0, 0, 0, 0};
    const int colq = 2 * (lane & 3);
    const int rowq = lane >> 2;
#pragma unroll
    for (int im = 0; im < 2; im++)
#pragma unroll
        for (int hh = 0; hh < 2; hh++) {
            const int r = mw * 32 + im * 16 + hh * 8 + rowq;
            const int sq = qid[r];
            const int slot = im * 2 + hh;
#pragma unroll
            for (int tl = 0; tl < 8; tl++)
#pragma unroll
                for (int e = 0; e < 2; e++) {
                    const float C = acc[im][tl][hh * 2 + e];
                    const int t = nw * 64 + tl * 8 + colq + e;
                    int d = sq - kid[t]; d = d < 0 ? -d : d;
                    const float ex = kf[t] * __expf(wt[d] * C);
                    pd[slot] += ex;
                    pn[slot] += ex * C;
                }
        }
#pragma unroll
    for (int o = 1; o <= 2; o <<= 1)
#pragma unroll
        for (int k = 0; k < 4; k++) {
            pn[k] += __shfl_xor_sync(0xffffffffu, pn[k], o);
            pd[k] += __shfl_xor_sync(0xffffffffu, pd[k], o);
        }
    if ((lane & 3) == 0)
#pragma unroll
        for (int k = 0; k < 4; k++) {
            const int r = mw * 32 + (k >> 1) * 16 + (k & 1) * 8 + rowq;
            nums[r * 4 + nw] = pn[k];
            dens[r * 4 + nw] = pd[k];
        }
    __syncthreads();
    if (tid < BM) {
        float n = 0.0f, d = 0.0f;
#pragma unroll
        for (int w = 0; w < 4; w++) { n += nums[tid * 4 + w]; d += dens[tid * 4 + w]; }
        float pt = d > 0.0f ? n / d : 0.0f;   // padded rows: n==0 -> 0
#pragma unroll
        for (int o = 16; o; o >>= 1) pt += __shfl_xor_sync(0xffffffffu, pt, o);
        if (lane == 0) wsum[tid >> 5] = pt;
    }
    __syncthreads();
    if (tid == 0) atomicAdd(&out[ib * NK + jb], wsum[0] + wsum[1]);
}

typedef CUresult (*EncodeFn)(CUtensorMap*, CUtensorMapDataType, cuuint32_t, void*,
                             const cuuint64_t*, const cuuint64_t*, const cuuint32_t*,
                             const cuuint32_t*, CUtensorMapInterleave, CUtensorMapSwizzle,
                             CUtensorMapL2promotion, CUtensorMapFloatOOBfill);

extern "C" void kernel_launch(void* const* d_in, const int* in_sizes, int n_in,
                              void* d_out, int out_size) {
    const float* q    = (const float*)d_in[0];
    const float* k    = (const float*)d_in[1];
    const float* lsc  = (const float*)d_in[2];
    const float* araw = (const float*)d_in[3];
    const int*   qm   = (const int*)d_in[4];
    const int*   km   = (const int*)d_in[5];
    float* out = (float*)d_out;

    void* qptr = nullptr; void* kptr = nullptr;
    cudaGetSymbolAddress(&qptr, g_qc);
    cudaGetSymbolAddress(&kptr, g_kc);
    EncodeFn enc = nullptr;
    cudaDriverEntryPointQueryResult qr;
#if CUDART_VERSION >= 12050
    cudaGetDriverEntryPointByVersion("cuTensorMapEncodeTiled", (void**)&enc, 12000,
                                     cudaEnableDefault, &qr);
#else
    cudaGetDriverEntryPoint("cuTensorMapEncodeTiled", (void**)&enc, cudaEnableDefault, &qr);
#endif
    CUtensorMap tmA, tmB;
    cuuint64_t gdA[2] = {(cuuint64_t)HDIM, (cuuint64_t)NB * SEQ};
    cuuint64_t gdB[2] = {(cuuint64_t)HDIM, (cuuint64_t)NK * SEQ};
    cuuint64_t gs[1]  = {(cuuint64_t)HDIM * 2};
    cuuint32_t boxA[2] = {64, 64}, boxB[2] = {64, 64}, es[2] = {1, 1};
    enc(&tmA, CU_TENSOR_MAP_DATA_TYPE_FLOAT16, 2, qptr, gdA, gs, boxA, es,
        CU_TENSOR_MAP_INTERLEAVE_NONE, CU_TENSOR_MAP_SWIZZLE_128B,
        CU_TENSOR_MAP_L2_PROMOTION_L2_128B, CU_TENSOR_MAP_FLOAT_OOB_FILL_NONE);
    enc(&tmB, CU_TENSOR_MAP_DATA_TYPE_FLOAT16, 2, kptr, gdB, gs, boxB, es,
        CU_TENSOR_MAP_INTERLEAVE_NONE, CU_TENSOR_MAP_SWIZZLE_128B,
        CU_TENSOR_MAP_L2_PROMOTION_L2_128B, CU_TENSOR_MAP_FLOAT_OOB_FILL_NONE);

    cudaFuncSetAttribute(li_hmma, cudaFuncAttributeMaxDynamicSharedMemorySize, SMEM_TOTAL);
    prep_kernel<<<NB + NK, 256>>>(qm, km, out);
    normalize_kernel<<<NB * SEQ + NK * SEQ, 192>>>(q, k);
    li_hmma<<<dim3(SEQ / BM, NK, NB), THREADS, SMEM_TOTAL>>>(tmA, tmB, lsc, araw, out);
}